// round 16
// baseline (speedup 1.0000x reference)
#include <cuda_runtime.h>
#include <cuda_fp16.h>
#include <math.h>

#define BB 8
#define NVV 500
#define NOO 1500
#define DVV 512
#define DOO 32
#define HH 128
#define EPSF 1e-5f
#define WV 16
#define WO 48

// ---------------- fp32 scratch ----------------
__device__ float g_cvp[3*BB*NVV*HH];
__device__ float g_zbuf[68000];       // [rvsum 4000][s1v 8000][s2v 8000][s1o 24000][s2o 24000]
__device__ float g_rv  [BB*NVV];
__device__ float g_to  [BB*NOO];
__device__ float g_e1v [BB*NVV];
__device__ float g_e2v [BB*NVV];
__device__ float g_e1o [BB*NOO];
__device__ float g_e2o [BB*NOO];
__device__ float g_smaxf[2*BB];
__device__ unsigned g_mv[BB*NVV*WV];
__device__ unsigned g_mo[BB*NOO*WO];

// ---------------- fp16 scratch ----------------
__device__ __half h_vism[BB*NVV*DVV];
__device__ __half h_objm[BB*NOO*DOO];
__device__ __half h_aov [BB*NOO*504];
__device__ __half h_aovt[BB*NVV*1504];
__device__ __half h_oT  [BB*HH*1504];
__device__ __half h_vT  [BB*HH*504];
__device__ __half h_hvT [BB*HH*504 + 32];
__device__ __half h_hoT [BB*HH*1504 + 32];
__device__ __half h_v   [BB*NVV*HH];
__device__ __half h_o   [BB*NOO*HH];
__device__ __half h_cv  [BB*NVV*HH];
__device__ __half h_co  [BB*NOO*HH];
__device__ __half h_m1v [BB*NVV*HH];
__device__ __half h_m1o [BB*NOO*HH];
__device__ __half h_vis [BB*NVV*HH];
__device__ __half h_obj [BB*NOO*HH];
__device__ __half g_wt  [237568];

#define WT_WV1 0
#define WT_WV2 65536
#define WT_WO1 81920
#define WT_WO2 86016
#define WT_O2G1 102400
#define WT_O2G2 118784
#define WT_G2O1 135168
#define WT_G2O2 151552
#define WT_IMG 167936
#define WT_OBJ 233472

// ---------------- helpers ----------------
__device__ __forceinline__ void mma16h(float* d, const unsigned* a, const unsigned* b) {
    asm volatile("mma.sync.aligned.m16n8k16.row.col.f32.f16.f16.f32 "
                 "{%0,%1,%2,%3},{%4,%5,%6,%7},{%8,%9},{%0,%1,%2,%3};"
                 : "+f"(d[0]), "+f"(d[1]), "+f"(d[2]), "+f"(d[3])
                 : "r"(a[0]), "r"(a[1]), "r"(a[2]), "r"(a[3]), "r"(b[0]), "r"(b[1]));
}
__device__ __forceinline__ void cpa16(unsigned dst, const void* src, int srcsz) {
    asm volatile("cp.async.cg.shared.global [%0], [%1], 16, %2;"
                 :: "r"(dst), "l"(src), "r"(srcsz));
}
__device__ __forceinline__ void cpa_commit() {
    asm volatile("cp.async.commit_group;");
}

// ---------------- fp16 GEMM: 64x64 tile, BK=32 halves, 256 threads, 4-stage ----------------
#define TBM 64
#define TBN 64
#define BKH 32
#define TSW 20
#define STAGES 4
#define TILEW (64*TSW)

struct GJ {
    const __half* A; const __half* Bt;
    float* Cf; __half* Ch;
    __half* CT; long ldCT; int Nrow;
    float* s1; float* s2; const float* a1; const float* a2;
    const float* bias; const __half* resh; const float* rowscale;
    int M, N, Ktot, Ksplit;
    int KpA, KpB;
    long sA, sB, sC;
    long spA, spB, spC;
    int nbat, nsplit, relu, gx, gy, total;
};

__device__ __forceinline__ void issue_tile_h(const GJ& j, const __half* Ab, const __half* Bb,
                                             int m0, int n0, int it, int Kact,
                                             unsigned aBase, unsigned bBase, int t)
{
    int row = t >> 2, c = t & 3;
    int gk = it * BKH + c * 8;
    int rem = Kact - gk;
    int sz = rem >= 8 ? 16 : (rem > 0 ? rem * 2 : 0);
    unsigned dstoff = (unsigned)(row * TSW + c * 4) * 4u;
    {
        int gm = m0 + row;
        int s = (gm < j.M) ? sz : 0;
        const __half* src = (gm < j.M) ? &Ab[(long)gm * j.KpA + gk] : Ab;
        cpa16(aBase + dstoff, src, s);
    }
    {
        int gn = n0 + row;
        int s = (gn < j.N) ? sz : 0;
        const __half* src = (gn < j.N) ? &Bb[(long)gn * j.KpB + gk] : Bb;
        cpa16(bBase + dstoff, src, s);
    }
}

__global__ void __launch_bounds__(256) gemm_h(GJ j0, GJ j1)
{
    __shared__ unsigned As[STAGES][TILEW];
    __shared__ unsigned Bs[STAGES][TILEW];

    GJ j; int bid;
    if (blockIdx.x < (unsigned)j0.total) { j = j0; bid = blockIdx.x; }
    else                                 { j = j1; bid = blockIdx.x - j0.total; }

    int per   = j.gx * j.gy;
    int bfull = bid / per;
    int rem   = bid - bfull * per;
    int by    = rem / j.gx;
    int bx    = rem - by * j.gx;
    int s     = bfull / j.nbat;
    int bb    = bfull - s * j.nbat;

    int Kact = j.Ktot - s * j.Ksplit;
    if (Kact > j.Ksplit) Kact = j.Ksplit;

    const __half* Ab = j.A  + (long)bb * j.sA + (long)s * j.spA;
    const __half* Bb = j.Bt + (long)bb * j.sB + (long)s * j.spB;
    long coff = (long)bb * j.sC + (long)s * j.spC;
    int m0 = by * TBM, n0 = bx * TBN;
    int M = j.M, N = j.N;

    int t = threadIdx.x;
    int warp = t >> 5, lane = t & 31;
    int g = lane >> 2, tg = lane & 3;
    int wm = warp >> 1, wn = warp & 1;

    float acc[4][4];
    #pragma unroll
    for (int ni = 0; ni < 4; ni++)
        #pragma unroll
        for (int e = 0; e < 4; e++) acc[ni][e] = 0.f;

    int ntiles = (Kact + BKH - 1) / BKH;

    #pragma unroll
    for (int st = 0; st < STAGES - 1; st++) {
        if (st < ntiles) {
            unsigned aB = (unsigned)__cvta_generic_to_shared(&As[st][0]);
            unsigned bB = (unsigned)__cvta_generic_to_shared(&Bs[st][0]);
            issue_tile_h(j, Ab, Bb, m0, n0, st, Kact, aB, bB, t);
        }
        cpa_commit();
    }

    for (int it = 0; it < ntiles; it++) {
        asm volatile("cp.async.wait_group %0;" :: "n"(STAGES - 2));
        __syncthreads();

        int nx = it + STAGES - 1;
        if (nx < ntiles) {
            unsigned aB = (unsigned)__cvta_generic_to_shared(&As[nx & (STAGES - 1)][0]);
            unsigned bB = (unsigned)__cvta_generic_to_shared(&Bs[nx & (STAGES - 1)][0]);
            issue_tile_h(j, Ab, Bb, m0, n0, nx, Kact, aB, bB, t);
        }
        cpa_commit();

        const unsigned* Asb = As[it & (STAGES - 1)];
        const unsigned* Bsb = Bs[it & (STAGES - 1)];

        #pragma unroll
        for (int kg = 0; kg < 2; kg++) {
            int kw = kg * 8;
            unsigned af[4], bf[4][2];
            int mb = wm * 16 + g;
            af[0] = Asb[mb * TSW + kw + tg];
            af[1] = Asb[(mb + 8) * TSW + kw + tg];
            af[2] = Asb[mb * TSW + kw + tg + 4];
            af[3] = Asb[(mb + 8) * TSW + kw + tg + 4];
            #pragma unroll
            for (int ni = 0; ni < 4; ni++) {
                int nb = wn * 32 + ni * 8 + g;
                bf[ni][0] = Bsb[nb * TSW + kw + tg];
                bf[ni][1] = Bsb[nb * TSW + kw + tg + 4];
            }
            #pragma unroll
            for (int ni = 0; ni < 4; ni++)
                mma16h(acc[ni], af, bf[ni]);
        }
    }

    #pragma unroll
    for (int hf = 0; hf < 2; hf++) {
        int row = m0 + wm * 16 + g + hf * 8;
        bool rok = row < M;
        float p1 = 0.f, p2 = 0.f;
        if (rok) {
            float scale = j.rowscale ? j.rowscale[bb * M + row] : 1.f;
            long tb0 = 0;
            if (j.CT) {
                int b2 = row / j.Nrow;
                int n2 = row - b2 * j.Nrow;
                tb0 = (long)b2 * HH * j.ldCT + n2;
            }
            long rowoff = coff + (long)row * N;
            #pragma unroll
            for (int ni = 0; ni < 4; ni++) {
                int col = n0 + wn * 32 + ni * 8 + tg * 2;
                if (col >= N) continue;
                float v0 = acc[ni][hf * 2 + 0] * scale;
                float v1 = acc[ni][hf * 2 + 1] * scale;
                if (j.bias) { v0 += j.bias[col]; v1 += j.bias[col + 1]; }
                long off = rowoff + col;
                if (j.resh) {
                    __half2 r = *(const __half2*)&j.resh[off];
                    float2 rf = __half22float2(r);
                    v0 += rf.x; v1 += rf.y;
                }
                if (j.relu) { v0 = v0 > 0.f ? v0 : 0.f; v1 = v1 > 0.f ? v1 : 0.f; }
                if (j.Cf) *(float2*)&j.Cf[off] = make_float2(v0, v1);
                if (j.Ch) *(__half2*)&j.Ch[off] = __floats2half2_rn(v0, v1);
                if (j.CT) {
                    long tb = tb0 + (long)col * j.ldCT;
                    j.CT[tb] = __float2half(v0);
                    j.CT[tb + j.ldCT] = __float2half(v1);
                }
                if (j.s1) {
                    p1 += v0 * j.a1[col] + v1 * j.a1[col + 1];
                    p2 += v0 * j.a2[col] + v1 * j.a2[col + 1];
                }
            }
        }
        if (j.s1) {
            p1 += __shfl_down_sync(0xffffffffu, p1, 2);
            p1 += __shfl_down_sync(0xffffffffu, p1, 1);
            p2 += __shfl_down_sync(0xffffffffu, p2, 2);
            p2 += __shfl_down_sync(0xffffffffu, p2, 1);
            if (tg == 0 && rok) {
                atomicAdd(&j.s1[row], p1);
                atomicAdd(&j.s2[row], p2);
            }
        }
    }
}

// ---------------- sprep: per-batch smax + factored exp tables ----------------
__global__ void sprep(const float* __restrict__ s2v, const float* __restrict__ s2o,
                      float* __restrict__ e1v, float* __restrict__ e2v,
                      float* __restrict__ e1o, float* __restrict__ e2o,
                      float* __restrict__ smaxf)
{
    __shared__ float red[256];
    int bx = blockIdx.x;
    const float* s2; float *E1, *E2; int N, b;
    if (bx < BB) { s2 = s2v; E1 = e1v; E2 = e2v; N = NVV; b = bx; }
    else         { s2 = s2o; E1 = e1o; E2 = e2o; N = NOO; b = bx - BB; }
    s2 += (long)b * N; E1 += (long)b * N; E2 += (long)b * N;
    float m = -1e30f;
    for (int i = threadIdx.x; i < N; i += 256) m = fmaxf(m, s2[i]);
    red[threadIdx.x] = m;
    __syncthreads();
    #pragma unroll
    for (int s = 128; s > 0; s >>= 1) {
        if (threadIdx.x < s) red[threadIdx.x] = fmaxf(red[threadIdx.x], red[threadIdx.x + s]);
        __syncthreads();
    }
    m = red[0];
    if (threadIdx.x == 0) smaxf[bx] = m;
    for (int i = threadIdx.x; i < N; i += 256) {
        float d = s2[i] - m;
        E1[i] = __expf(d);
        E2[i] = __expf(0.2f * d);
    }
}

// ---------------- merged prologue: maskbuild | aovprep | cvtflat x2 | wcvt ----------------
#define NB_MASK 2000
#define NB_AOV  (16*47*BB)
#define NB_CVV  2000
#define NB_CVO  375
#define NB_W    640
#define NB_PREP (NB_MASK + NB_AOV + NB_CVV + NB_CVO + NB_W)

struct WJobs { const float* src[10]; int K[10]; int N[10]; long off[10]; };

__global__ void __launch_bounds__(256) prep(
    const float* __restrict__ adjv, const float* __restrict__ adjo,
    unsigned* __restrict__ mv, unsigned* __restrict__ mo,
    const float* __restrict__ Aov, __half* __restrict__ aov,
    __half* __restrict__ aovt, float* __restrict__ csum,
    const float* __restrict__ vism, __half* __restrict__ vismh,
    const float* __restrict__ objm, __half* __restrict__ objmh,
    WJobs w, __half* __restrict__ arena)
{
    __shared__ float tl[32][33];
    int bidx = blockIdx.x;
    int tid = threadIdx.x;

    if (bidx < NB_MASK) {
        int warp = tid >> 5, lane = tid & 31;
        long gw = (long)bidx * 8 + warp;
        const float* adj; unsigned* m; int N, W; long row;
        if (gw < (long)BB * NVV) { adj = adjv; m = mv; N = NVV; W = WV; row = gw; }
        else                     { adj = adjo; m = mo; N = NOO; W = WO; row = gw - (long)BB * NVV; }
        const float* ar = adj + row * (long)N;
        unsigned* mr = m + row * (long)W;
        int nit = (W + 3) / 4;
        for (int it = 0; it < nit; it++) {
            int j0 = it * 128 + lane * 4;
            unsigned nib = 0;
            if (j0 + 3 < N) {
                float4 a = *(const float4*)&ar[j0];
                if (a.x > 0.f) nib |= 1u;
                if (a.y > 0.f) nib |= 2u;
                if (a.z > 0.f) nib |= 4u;
                if (a.w > 0.f) nib |= 8u;
            } else {
                #pragma unroll
                for (int e = 0; e < 4; e++)
                    if (j0 + e < N && ar[j0 + e] > 0.f) nib |= 1u << e;
            }
            unsigned v = nib << ((lane & 7) * 4);
            v |= __shfl_xor_sync(0xffffffffu, v, 1);
            v |= __shfl_xor_sync(0xffffffffu, v, 2);
            v |= __shfl_xor_sync(0xffffffffu, v, 4);
            if ((lane & 7) == 0) {
                int ww = it * 4 + (lane >> 3);
                if (ww < W) mr[ww] = v;
            }
        }
        return;
    }
    bidx -= NB_MASK;
    if (bidx < NB_AOV) {
        int b = bidx / (16 * 47);
        int r2 = bidx - b * (16 * 47);
        int yb = r2 / 16;
        int xb = r2 - yb * 16;
        int v0 = xb * 32, o0 = yb * 32;
        int tx = tid & 31, ty = tid >> 5;
        const float* Ab = Aov + (long)b * NOO * NVV;
        #pragma unroll
        for (int i = 0; i < 4; i++) {
            int o = o0 + ty + i * 8, v = v0 + tx;
            tl[ty + i * 8][tx] = (o < NOO && v < NVV) ? Ab[(long)o * NVV + v] : 0.f;
        }
        __syncthreads();
        #pragma unroll
        for (int i = 0; i < 4; i++) {
            int o = o0 + ty + i * 8, v = v0 + tx;
            if (o < NOO && v < 504)
                aov[(long)b * NOO * 504 + (long)o * 504 + v] = __float2half(tl[ty + i * 8][tx]);
        }
        #pragma unroll
        for (int i = 0; i < 4; i++) {
            int v = v0 + ty + i * 8, o = o0 + tx;
            if (v < NVV)
                aovt[(long)b * NVV * 1504 + (long)v * 1504 + o] = __float2half(tl[tx][ty + i * 8]);
        }
        if (ty == 0 && v0 + tx < NVV) {
            float s = 0.f;
            #pragma unroll
            for (int o = 0; o < 32; o++) s += tl[o][tx];
            atomicAdd(&csum[b * NVV + v0 + tx], s);
        }
        return;
    }
    bidx -= NB_AOV;
    if (bidx < NB_CVV + NB_CVO) {
        const float* src; __half* dst; long n4; long i0;
        if (bidx < NB_CVV) { src = vism; dst = vismh; n4 = (long)BB * NVV * DVV / 4; i0 = (long)bidx * 256; }
        else { src = objm; dst = objmh; n4 = (long)BB * NOO * DOO / 4; i0 = (long)(bidx - NB_CVV) * 256; }
        long i = i0 + tid;
        if (i < n4) {
            float4 v = *(const float4*)&src[i * 4];
            __half2 h0 = __floats2half2_rn(v.x, v.y);
            __half2 h1 = __floats2half2_rn(v.z, v.w);
            uint2 u;
            u.x = *(unsigned*)&h0;
            u.y = *(unsigned*)&h1;
            *(uint2*)&dst[i * 4] = u;
        }
        return;
    }
    bidx -= NB_CVV + NB_CVO;
    {
        int jid = bidx / 64;
        int xb = bidx - jid * 64;
        const float* s = w.src[jid];
        int K = w.K[jid], N = w.N[jid];
        long off = w.off[jid];
        long n = (long)K * N;
        for (long idx = (long)xb * 256 + tid; idx < n; idx += 64L * 256) {
            long k = idx / N;
            int c = (int)(idx - k * N);
            arena[off + (long)c * K + k] = __float2half(s[idx]);
        }
    }
}

// ---------------- fp16 fused masked-softmax attention (factored exp) ----------------
#define AROWS 64
#define AJC 128
#define HS2 68
#define ATTN_SMEM_H ((128*HS2 + AROWS*HS2 + AROWS) * 4)

struct AJob {
    const __half* hT; const float* s1; const float* s2;
    const float* E1; const float* E2; const float* smaxf;
    __half* out; __half* outT; const float* tsc;
    const unsigned* mask; int W;
    long ldT; int N; int nx; int total;
};

__global__ void __launch_bounds__(256) attn_h(AJob j0, AJob j1)
{
    extern __shared__ unsigned smu[];
    unsigned* hsT = smu;
    unsigned* wsh = smu + 128 * HS2;
    float* zrow   = (float*)(wsh + AROWS * HS2);

    AJob j; int bid;
    if (blockIdx.x < (unsigned)j0.total) { j = j0; bid = blockIdx.x; }
    else                                 { j = j1; bid = blockIdx.x - j0.total; }
    int b  = bid / j.nx;
    int i0 = (bid - b * j.nx) * AROWS;
    int N  = j.N;

    int t = threadIdx.x;
    int warp = t >> 5, lane = t & 31;
    int g = lane >> 2, tg = lane & 3;
    int wm = warp >> 2, wn = warp & 3;

    const __half* hTb  = j.hT + (long)b * HH * j.ldT;
    const float* s2b   = j.s2 + (long)b * N;
    const float* E1b   = j.E1 + (long)b * N;
    const float* E2b   = j.E2 + (long)b * N;
    unsigned hsBase = (unsigned)__cvta_generic_to_shared(hsT);

    float acc[2][4][4];
    #pragma unroll
    for (int mi = 0; mi < 2; mi++)
        #pragma unroll
        for (int ni = 0; ni < 4; ni++)
            #pragma unroll
            for (int e = 0; e < 4; e++) acc[mi][ni][e] = 0.f;

    if (t < AROWS) zrow[t] = 0.f;

    int pr = t >> 2;
    int pj = (t & 3) * 32;
    int prow = i0 + pr;
    float thr = 0.f, c1 = 0.f, c2 = 0.f;
    if (prow < N) {
        float s1r = j.s1[(long)b * N + prow];
        float x = s1r + j.smaxf[b];
        float mrow = x > 0.f ? x : 0.2f * x;
        c1 = __expf(x - mrow);          // == exp(s1+smax-m), <= 1
        c2 = __expf(0.2f * x - mrow);   // <= 1
        thr = -s1r;
    }

    int sf = t >> 1;
    int ss = (t & 1) * 64;

    for (int c0 = 0; c0 < N; c0 += AJC) {
        __syncthreads();

        {
            const __half* src = hTb + (long)sf * j.ldT + c0 + ss;
            unsigned dst = hsBase + (unsigned)(sf * HS2) * 4u + (unsigned)ss * 2u;
            #pragma unroll
            for (int s = 0; s < 8; s++)
                cpa16(dst + s * 16u, src + s * 8, 16);
            cpa_commit();
        }

        float zl = 0.f;
        if (prow < N) {
            long mbase = ((long)b * N + prow) * j.W + (c0 >> 5) + (t & 3);
            int wbase = pr * HS2 + (pj >> 1);
            unsigned mw = j.mask[mbase];
            if (mw) {
                #pragma unroll
                for (int q4 = 0; q4 < 32; q4 += 4) {
                    int jj = pj + q4;
                    int gj = c0 + jj;
                    float sv[4], e1[4], e2[4];
                    if (gj + 3 < N) {
                        float4 s4 = *(const float4*)&s2b[gj];
                        float4 a4 = *(const float4*)&E1b[gj];
                        float4 b4 = *(const float4*)&E2b[gj];
                        sv[0]=s4.x; sv[1]=s4.y; sv[2]=s4.z; sv[3]=s4.w;
                        e1[0]=a4.x; e1[1]=a4.y; e1[2]=a4.z; e1[3]=a4.w;
                        e2[0]=b4.x; e2[1]=b4.y; e2[2]=b4.z; e2[3]=b4.w;
                    } else {
                        #pragma unroll
                        for (int e = 0; e < 4; e++) {
                            bool ok = (gj + e) < N;
                            sv[e] = ok ? s2b[gj + e] : 0.f;
                            e1[e] = ok ? E1b[gj + e] : 0.f;
                            e2[e] = ok ? E2b[gj + e] : 0.f;
                        }
                    }
                    float w[4];
                    #pragma unroll
                    for (int e = 0; e < 4; e++) {
                        w[e] = 0.f;
                        if ((mw >> (q4 + e)) & 1u)
                            w[e] = (sv[e] > thr) ? c1 * e1[e] : c2 * e2[e];
                    }
                    __half2 u0 = __floats2half2_rn(w[0], w[1]);
                    __half2 u1 = __floats2half2_rn(w[2], w[3]);
                    *(__half2*)&wsh[wbase + (q4 >> 1)]     = u0;
                    *(__half2*)&wsh[wbase + (q4 >> 1) + 1] = u1;
                    float2 f0 = __half22float2(u0), f1 = __half22float2(u1);
                    zl += f0.x + f0.y + f1.x + f1.y;
                }
            } else {
                #pragma unroll
                for (int q = 0; q < 16; q++) wsh[wbase + q] = 0u;
            }
        } else {
            int wbase = pr * HS2 + (pj >> 1);
            #pragma unroll
            for (int q = 0; q < 16; q++) wsh[wbase + q] = 0u;
        }
        zl += __shfl_down_sync(0xffffffffu, zl, 2);
        zl += __shfl_down_sync(0xffffffffu, zl, 1);
        if ((t & 3) == 0 && prow < N) zrow[pr] += zl;

        asm volatile("cp.async.wait_group 0;");
        __syncthreads();

        #pragma unroll
        for (int kg = 0; kg < 8; kg++) {
            int kw = kg * 8;
            unsigned af[2][4], bf[4][2];
            #pragma unroll
            for (int mi = 0; mi < 2; mi++) {
                int mr = wm * 32 + mi * 16 + g;
                af[mi][0] = wsh[mr * HS2 + kw + tg];
                af[mi][1] = wsh[(mr + 8) * HS2 + kw + tg];
                af[mi][2] = wsh[mr * HS2 + kw + tg + 4];
                af[mi][3] = wsh[(mr + 8) * HS2 + kw + tg + 4];
            }
            #pragma unroll
            for (int ni = 0; ni < 4; ni++) {
                int nr = wn * 32 + ni * 8 + g;
                bf[ni][0] = hsT[nr * HS2 + kw + tg];
                bf[ni][1] = hsT[nr * HS2 + kw + tg + 4];
            }
            #pragma unroll
            for (int mi = 0; mi < 2; mi++)
                #pragma unroll
                for (int ni = 0; ni < 4; ni++)
                    mma16h(acc[mi][ni], af[mi], bf[ni]);
        }
    }
    __syncthreads();

    long tbb = (long)b * HH * j.ldT;
    #pragma unroll
    for (int mi = 0; mi < 2; mi++) {
        #pragma unroll
        for (int hf = 0; hf < 2; hf++) {
            int r0 = wm * 32 + mi * 16 + g + hf * 8;
            int row = i0 + r0;
            if (row >= N) continue;
            float inv = 1.f / zrow[r0];
            float rs = j.tsc ? j.tsc[(long)b * N + row] : 1.f;
            long tb0 = tbb + row;
            #pragma unroll
            for (int ni = 0; ni < 4; ni++) {
                int col = wn * 32 + ni * 8 + tg * 2;
                float v0 = acc[mi][ni][hf * 2 + 0] * inv;
                float v1 = acc[mi][ni][hf * 2 + 1] * inv;
                v0 = v0 > 0.f ? v0 : 0.f;
                v1 = v1 > 0.f ? v1 : 0.f;
                long off = (long)b * N * HH + (long)row * HH + col;
                *(__half2*)&j.out[off] = __floats2half2_rn(v0, v1);
                j.outT[tb0 + (long)col * j.ldT]       = __float2half(v0 * rs);
                j.outT[tb0 + (long)(col + 1) * j.ldT] = __float2half(v1 * rs);
            }
        }
    }
}

// ---------------- remaining helpers ----------------
__global__ void cvred(const float* __restrict__ p, const float* __restrict__ rv,
                      __half* __restrict__ cv)
{
    int i = blockIdx.x * 256 + threadIdx.x;
    if (i < BB * NVV * HH) {
        float s = p[i] + p[i + BB*NVV*HH] + p[i + 2*BB*NVV*HH];
        cv[i] = __float2half(s * rv[i >> 7]);
    }
}

__global__ void rvfin_kernel(const float* __restrict__ sums, float* __restrict__ rv, int n)
{
    int i = blockIdx.x * 256 + threadIdx.x;
    if (i < n) rv[i] = 1.f / (sums[i] + EPSF);
}

__global__ void rowsum_h(const __half* __restrict__ aov, const float* __restrict__ rv,
                         float* __restrict__ to_)
{
    int warp = threadIdx.x >> 5, lane = threadIdx.x & 31;
    int o = blockIdx.x * 8 + warp;
    int b = blockIdx.y;
    if (o >= NOO) return;
    const __half2* row = (const __half2*)(aov + (long)b * NOO * 504 + (long)o * 504);
    const float2* rvb = (const float2*)(rv + b * NVV);
    float s = 0.f;
    #pragma unroll
    for (int i = 0; i < 8; i++) {
        int idx = lane + 32 * i;
        if (idx < 250) {
            float2 f = __half22float2(row[idx]);
            float2 r = rvb[idx];
            s += f.x * r.x + f.y * r.y;
        }
    }
    #pragma unroll
    for (int off = 16; off; off >>= 1) s += __shfl_xor_sync(0xffffffffu, s, off);
    if (lane == 0) to_[b * NOO + o] = 1.f / (s + EPSF);
}

// ---------------- host orchestration ----------------
static GJ mkjob(const __half* A, const __half* Bt, float* Cf, __half* Ch,
                const float* bias, const __half* resh, const float* rowscale,
                int M, int N, int K, int KpA, int KpB,
                long sA, long sB, long sC, int relu, int nbat)
{
    GJ j;
    j.A = A; j.Bt = Bt; j.Cf = Cf; j.Ch = Ch;
    j.CT = nullptr; j.ldCT = 0; j.Nrow = 1;
    j.s1 = nullptr; j.s2 = nullptr; j.a1 = nullptr; j.a2 = nullptr;
    j.bias = bias; j.resh = resh; j.rowscale = rowscale;
    j.M = M; j.N = N; j.Ktot = K; j.Ksplit = K;
    j.KpA = KpA; j.KpB = KpB;
    j.sA = sA; j.sB = sB; j.sC = sC;
    j.spA = 0; j.spB = 0; j.spC = 0;
    j.nbat = nbat; j.nsplit = 1; j.relu = relu;
    j.gx = (N + TBN - 1) / TBN;
    j.gy = (M + TBM - 1) / TBM;
    j.total = j.gx * j.gy * nbat;
    return j;
}

static void launch_gemm2(const GJ& a, const GJ& b)
{
    gemm_h<<<a.total + b.total, 256>>>(a, b);
}

extern "C" void kernel_launch(void* const* d_in, const int* in_sizes, int n_in,
                              void* d_out, int out_size)
{
    const float* vis_memory = (const float*)d_in[0];
    const float* obj_memory = (const float*)d_in[1];
    const float* vis_adj    = (const float*)d_in[2];
    const float* obj_adj    = (const float*)d_in[3];
    const float* A_OV       = (const float*)d_in[4];
    const float* Wv1  = (const float*)d_in[5];
    const float* av1a = (const float*)d_in[6];
    const float* av1b = (const float*)d_in[7];
    const float* Wv2  = (const float*)d_in[8];
    const float* av2a = (const float*)d_in[9];
    const float* av2b = (const float*)d_in[10];
    const float* Wo1  = (const float*)d_in[11];
    const float* ao1a = (const float*)d_in[12];
    const float* ao1b = (const float*)d_in[13];
    const float* Wo2  = (const float*)d_in[14];
    const float* ao2a = (const float*)d_in[15];
    const float* ao2b = (const float*)d_in[16];
    const float* g2o_W1 = (const float*)d_in[17];
    const float* g2o_b1 = (const float*)d_in[18];
    const float* g2o_W2 = (const float*)d_in[19];
    const float* g2o_b2 = (const float*)d_in[20];
    const float* o2g_W1 = (const float*)d_in[21];
    const float* o2g_b1 = (const float*)d_in[22];
    const float* o2g_W2 = (const float*)d_in[23];
    const float* o2g_b2 = (const float*)d_in[24];
    const float* img_W = (const float*)d_in[25];
    const float* img_b = (const float*)d_in[26];
    const float* obj_W = (const float*)d_in[27];
    const float* obj_b = (const float*)d_in[28];

    float *p_cvp, *p_zbuf, *p_rv, *p_to, *p_e1v, *p_e2v, *p_e1o, *p_e2o, *p_smaxf;
    unsigned *p_mv, *p_mo;
    __half *ph_vism, *ph_objm, *ph_aov, *ph_aovt, *ph_oT, *ph_vT, *ph_hvT, *ph_hoT;
    __half *ph_v, *ph_o, *ph_cv, *ph_co, *ph_m1v, *ph_m1o, *ph_vis, *ph_obj, *ph_wt;

    cudaGetSymbolAddress((void**)&p_cvp, g_cvp);
    cudaGetSymbolAddress((void**)&p_zbuf, g_zbuf);
    cudaGetSymbolAddress((void**)&p_rv,  g_rv);
    cudaGetSymbolAddress((void**)&p_to,  g_to);
    cudaGetSymbolAddress((void**)&p_e1v, g_e1v);
    cudaGetSymbolAddress((void**)&p_e2v, g_e2v);
    cudaGetSymbolAddress((void**)&p_e1o, g_e1o);
    cudaGetSymbolAddress((void**)&p_e2o, g_e2o);
    cudaGetSymbolAddress((void**)&p_smaxf, g_smaxf);
    cudaGetSymbolAddress((void**)&p_mv,  g_mv);
    cudaGetSymbolAddress((void**)&p_mo,  g_mo);
    cudaGetSymbolAddress((void**)&ph_vism, h_vism);
    cudaGetSymbolAddress((void**)&ph_objm, h_objm);
    cudaGetSymbolAddress((void**)&ph_aov,  h_aov);
    cudaGetSymbolAddress((void**)&ph_aovt, h_aovt);
    cudaGetSymbolAddress((void**)&ph_oT,   h_oT);
    cudaGetSymbolAddress((void**)&ph_vT,   h_vT);
    cudaGetSymbolAddress((void**)&ph_hvT,  h_hvT);
    cudaGetSymbolAddress((void**)&ph_hoT,  h_hoT);
    cudaGetSymbolAddress((void**)&ph_v,    h_v);
    cudaGetSymbolAddress((void**)&ph_o,    h_o);
    cudaGetSymbolAddress((void**)&ph_cv,   h_cv);
    cudaGetSymbolAddress((void**)&ph_co,   h_co);
    cudaGetSymbolAddress((void**)&ph_m1v,  h_m1v);
    cudaGetSymbolAddress((void**)&ph_m1o,  h_m1o);
    cudaGetSymbolAddress((void**)&ph_vis,  h_vis);
    cudaGetSymbolAddress((void**)&ph_obj,  h_obj);
    cudaGetSymbolAddress((void**)&ph_wt,   g_wt);

    float* p_rvsum = p_zbuf;
    float* ps1v = p_zbuf + 4000;
    float* ps2v = p_zbuf + 12000;
    float* ps1o = p_zbuf + 20000;
    float* ps2o = p_zbuf + 44000;

    cudaFuncSetAttribute(attn_h, cudaFuncAttributeMaxDynamicSharedMemorySize, ATTN_SMEM_H);

    // ---- prologue ----
    cudaMemsetAsync(p_zbuf, 0, 68000 * sizeof(float));
    {
        WJobs w;
        const float* srcs[10] = { Wv1, Wv2, Wo1, Wo2, o2g_W1, o2g_W2, g2o_W1, g2o_W2, img_W, obj_W };
        int Ks[10] = { 512, 128, 32, 128, 128, 128, 128, 128, 128, 128 };
        int Ns[10] = { 128, 128, 128, 128, 128, 128, 128, 128, 512, 32 };
        long offs[10] = { WT_WV1, WT_WV2, WT_WO1, WT_WO2, WT_O2G1, WT_O2G2,
                          WT_G2O1, WT_G2O2, WT_IMG, WT_OBJ };
        for (int i = 0; i < 10; i++) { w.src[i] = srcs[i]; w.K[i] = Ks[i]; w.N[i] = Ns[i]; w.off[i] = offs[i]; }
        prep<<<NB_PREP, 256>>>(vis_adj, obj_adj, p_mv, p_mo,
                               A_OV, ph_aov, ph_aovt, p_rvsum,
                               vis_memory, ph_vism, obj_memory, ph_objm,
                               w, ph_wt);
    }
    rvfin_kernel<<<(BB * NVV + 255) / 256, 256>>>(p_rvsum, p_rv, BB * NVV);
    rowsum_h<<<dim3((NOO + 7) / 8, BB), 256>>>(ph_aov, p_rv, p_to);

    for (int round = 0; round < 2; round++) {
        const __half* xv = (round == 0) ? ph_vism : ph_vis;
        const __half* xo = (round == 0) ? ph_objm : ph_obj;
        int Kv = (round == 0) ? DVV : HH;
        int Ko = (round == 0) ? DOO : HH;
        const __half* Wvt = ph_wt + ((round == 0) ? WT_WV1 : WT_WV2);
        const __half* Wot = ph_wt + ((round == 0) ? WT_WO1 : WT_WO2);
        const float* ava = (round == 0) ? av1a : av2a;
        const float* avb = (round == 0) ? av1b : av2b;
        const float* aoa = (round == 0) ? ao1a : ao2a;
        const float* aob = (round == 0) ? ao1b : ao2b;
        float* s1v = ps1v + round * BB * NVV;
        float* s2v = ps2v + round * BB * NVV;
        float* s1o = ps1o + round * BB * NOO;
        float* s2o = ps2o + round * BB * NOO;

        // h = x @ W  (transposed fp16 out + fused scores)
        {
            GJ jv = mkjob(xv, Wvt, nullptr, nullptr, nullptr, nullptr, nullptr,
                          BB * NVV, HH, Kv, Kv, Kv, 0, 0, 0, 0, 1);
            jv.CT = ph_hvT; jv.ldCT = 504; jv.Nrow = NVV;
            jv.s1 = s1v; jv.s2 = s2v; jv.a1 = ava; jv.a2 = avb;
            GJ jo = mkjob(xo, Wot, nullptr, nullptr, nullptr, nullptr, nullptr,
                          BB * NOO, HH, Ko, Ko, Ko, 0, 0, 0, 0, 1);
            jo.CT = ph_hoT; jo.ldCT = 1504; jo.Nrow = NOO;
            jo.s1 = s1o; jo.s2 = s2o; jo.a1 = aoa; jo.a2 = aob;
            launch_gemm2(jv, jo);
        }

        // factored-exp tables + per-batch smax (one launch, both sides)
        sprep<<<2 * BB, 256>>>(s2v, s2o, p_e1v, p_e2v, p_e1o, p_e2o, p_smaxf);

        // attention (fp16 mma, mask-based, factored exp); obj job first (long blocks)
        {
            int nxv = (NVV + AROWS - 1) / AROWS;
            int nxo = (NOO + AROWS - 1) / AROWS;
            AJob ao_ = { ph_hoT, s1o, s2o, p_e1o, p_e2o, p_smaxf + BB,
                         ph_o, ph_oT, nullptr, p_mo, WO, 1504, NOO, nxo, nxo * BB };
            AJob av_ = { ph_hvT, s1v, s2v, p_e1v, p_e2v, p_smaxf,
                         ph_v, ph_vT, p_rv, p_mv, WV, 504, NVV, nxv, nxv * BB };
            attn_h<<<ao_.total + av_.total, 256, ATTN_SMEM_H>>>(ao_, av_);
        }

        // cv partials (split-K x3 @512) || co = to ⊙ (A_OV @ (rv⊙v))
        {
            GJ jcv = mkjob(ph_aovt, ph_oT, p_cvp, nullptr, nullptr, nullptr, nullptr,
                           NVV, HH, NOO, 1504, 1504,
                           (long)NVV * 1504, (long)HH * 1504, (long)NVV * HH, 0, BB);
            jcv.Ksplit = 512; jcv.nsplit = 3;
            jcv.spA = 512; jcv.spB = 512; jcv.spC = (long)BB * NVV * HH;
            jcv.total = jcv.gx * jcv.gy * BB * 3;
            GJ jco = mkjob(ph_aov, ph_vT, nullptr, ph_co, nullptr, nullptr, p_to,
                           NOO, HH, NVV, 504, 504,
                           (long)NOO * 504, (long)HH * 504, (long)NOO * HH, 0, BB);
            launch_gemm2(jcv, jco);
        }
        cvred<<<(BB * NVV * HH + 255) / 256, 256>>>(p_cvp, p_rv, ph_cv);

        // mlp layer 1 (relu)
        launch_gemm2(
            mkjob(ph_cv, ph_wt + WT_O2G1, nullptr, ph_m1v, o2g_b1, nullptr, nullptr,
                  BB * NVV, HH, HH, HH, HH, 0, 0, 0, 1, 1),
            mkjob(ph_co, ph_wt + WT_G2O1, nullptr, ph_m1o, g2o_b1, nullptr, nullptr,
                  BB * NOO, HH, HH, HH, HH, 0, 0, 0, 1, 1));

        // mlp layer 2 + fp16 residual
        launch_gemm2(
            mkjob(ph_m1v, ph_wt + WT_O2G2, nullptr, ph_vis, o2g_b2, ph_v, nullptr,
                  BB * NVV, HH, HH, HH, HH, 0, 0, 0, 0, 1),
            mkjob(ph_m1o, ph_wt + WT_G2O2, nullptr, ph_obj, g2o_b2, ph_o, nullptr,
                  BB * NOO, HH, HH, HH, HH, 0, 0, 0, 0, 1));
    }

    // output projections
    float* out_vis = (float*)d_out;
    float* out_obj = out_vis + (long)BB * NVV * DVV;
    launch_gemm2(
        mkjob(ph_vis, ph_wt + WT_IMG, out_vis, nullptr, img_b, nullptr, nullptr,
              BB * NVV, DVV, HH, HH, HH, 0, 0, 0, 0, 1),
        mkjob(ph_obj, ph_wt + WT_OBJ, out_obj, nullptr, obj_b, nullptr, nullptr,
              BB * NOO, DOO, HH, HH, HH, 0, 0, 0, 0, 1));
}

// round 17
// speedup vs baseline: 1.0536x; 1.0536x over previous
#include <cuda_runtime.h>
#include <cuda_fp16.h>
#include <math.h>

#define BB 8
#define NVV 500
#define NOO 1500
#define DVV 512
#define DOO 32
#define HH 128
#define EPSF 1e-5f
#define WV 16
#define WO 48

// ---------------- fp32 scratch ----------------
__device__ float g_cvp[3*BB*NVV*HH];
__device__ float g_zbuf[68000];       // [rvsum 4000][s1v 8000][s2v 8000][s1o 24000][s2o 24000]
__device__ float g_rv  [BB*NVV];
__device__ float g_to  [BB*NOO];
__device__ unsigned g_mv[BB*NVV*WV];
__device__ unsigned g_mo[BB*NOO*WO];

// ---------------- fp16 scratch ----------------
__device__ __half h_vism[BB*NVV*DVV];
__device__ __half h_objm[BB*NOO*DOO];
__device__ __half h_aov [BB*NOO*504];
__device__ __half h_aovt[BB*NVV*1504];
__device__ __half h_oT  [BB*HH*1504];
__device__ __half h_vT  [BB*HH*504];
__device__ __half h_hvT [BB*HH*504 + 32];
__device__ __half h_hoT [BB*HH*1504 + 32];
__device__ __half h_v   [BB*NVV*HH];
__device__ __half h_o   [BB*NOO*HH];
__device__ __half h_co  [BB*NOO*HH];
__device__ __half h_m1v [BB*NVV*HH];
__device__ __half h_m1o [BB*NOO*HH];
__device__ __half h_vis [BB*NVV*HH];
__device__ __half h_obj [BB*NOO*HH];
__device__ __half g_wt  [237568];

#define WT_WV1 0
#define WT_WV2 65536
#define WT_WO1 81920
#define WT_WO2 86016
#define WT_O2G1 102400
#define WT_O2G2 118784
#define WT_G2O1 135168
#define WT_G2O2 151552
#define WT_IMG 167936
#define WT_OBJ 233472

// ---------------- helpers ----------------
__device__ __forceinline__ void mma16h(float* d, const unsigned* a, const unsigned* b) {
    asm volatile("mma.sync.aligned.m16n8k16.row.col.f32.f16.f16.f32 "
                 "{%0,%1,%2,%3},{%4,%5,%6,%7},{%8,%9},{%0,%1,%2,%3};"
                 : "+f"(d[0]), "+f"(d[1]), "+f"(d[2]), "+f"(d[3])
                 : "r"(a[0]), "r"(a[1]), "r"(a[2]), "r"(a[3]), "r"(b[0]), "r"(b[1]));
}
__device__ __forceinline__ void cpa16(unsigned dst, const void* src, int srcsz) {
    asm volatile("cp.async.cg.shared.global [%0], [%1], 16, %2;"
                 :: "r"(dst), "l"(src), "r"(srcsz));
}
__device__ __forceinline__ void cpa_commit() {
    asm volatile("cp.async.commit_group;");
}

// ---------------- fp16 GEMM: 64x64 tile, BK=32 halves, 256 threads, 4-stage ----------------
#define TBM 64
#define TBN 64
#define BKH 32
#define TSW 20
#define STAGES 4
#define TILEW (64*TSW)

struct GJ {
    const __half* A; const __half* Bt;
    float* Cf; __half* Ch;
    __half* CT; long ldCT; int Nrow;
    float* s1; float* s2; const float* a1; const float* a2;
    const float* Ap3; const float* aprv;      // fused cv-partial A path
    const float* bias; const __half* resh; const float* rowscale;
    int M, N, Ktot, Ksplit;
    int KpA, KpB;
    long sA, sB, sC;
    long spA, spB, spC;
    int nbat, nsplit, relu, gx, gy, total;
};

__device__ __forceinline__ void issue_tile_h(const GJ& j, const __half* Ab, const __half* Bb,
                                             int m0, int n0, int it, int Kact,
                                             unsigned aBase, unsigned bBase, int t)
{
    int row = t >> 2, c = t & 3;
    int gk = it * BKH + c * 8;
    int rem = Kact - gk;
    int sz = rem >= 8 ? 16 : (rem > 0 ? rem * 2 : 0);
    unsigned dstoff = (unsigned)(row * TSW + c * 4) * 4u;
    if (!j.Ap3) {
        int gm = m0 + row;
        int s = (gm < j.M) ? sz : 0;
        const __half* src = (gm < j.M) ? &Ab[(long)gm * j.KpA + gk] : Ab;
        cpa16(aBase + dstoff, src, s);
    }
    {
        int gn = n0 + row;
        int s = (gn < j.N) ? sz : 0;
        const __half* src = (gn < j.N) ? &Bb[(long)gn * j.KpB + gk] : Bb;
        cpa16(bBase + dstoff, src, s);
    }
}

__global__ void __launch_bounds__(256) gemm_h(GJ j0, GJ j1)
{
    __shared__ unsigned As[STAGES][TILEW];
    __shared__ unsigned Bs[STAGES][TILEW];

    GJ j; int bid;
    if (blockIdx.x < (unsigned)j0.total) { j = j0; bid = blockIdx.x; }
    else                                 { j = j1; bid = blockIdx.x - j0.total; }

    int per   = j.gx * j.gy;
    int bfull = bid / per;
    int rem   = bid - bfull * per;
    int by    = rem / j.gx;
    int bx    = rem - by * j.gx;
    int s     = bfull / j.nbat;
    int bb    = bfull - s * j.nbat;

    int Kact = j.Ktot - s * j.Ksplit;
    if (Kact > j.Ksplit) Kact = j.Ksplit;

    const __half* Ab = j.A  + (long)bb * j.sA + (long)s * j.spA;
    const __half* Bb = j.Bt + (long)bb * j.sB + (long)s * j.spB;
    long coff = (long)bb * j.sC + (long)s * j.spC;
    int m0 = by * TBM, n0 = bx * TBN;
    int M = j.M, N = j.N;

    int t = threadIdx.x;
    int warp = t >> 5, lane = t & 31;
    int g = lane >> 2, tg = lane & 3;
    int wm = warp >> 1, wn = warp & 1;

    float acc[4][4];
    #pragma unroll
    for (int ni = 0; ni < 4; ni++)
        #pragma unroll
        for (int e = 0; e < 4; e++) acc[ni][e] = 0.f;

    int ntiles = (Kact + BKH - 1) / BKH;

    #pragma unroll
    for (int st = 0; st < STAGES - 1; st++) {
        if (st < ntiles) {
            unsigned aB = (unsigned)__cvta_generic_to_shared(&As[st][0]);
            unsigned bB = (unsigned)__cvta_generic_to_shared(&Bs[st][0]);
            issue_tile_h(j, Ab, Bb, m0, n0, st, Kact, aB, bB, t);
        }
        cpa_commit();
    }

    for (int it = 0; it < ntiles; it++) {
        asm volatile("cp.async.wait_group %0;" :: "n"(STAGES - 2));
        __syncthreads();

        if (j.Ap3) {
            // fill A tile for `it` from 3 fp32 cv-partials, scaled by rv
            int row = t >> 2, c = t & 3;
            int gm = m0 + row;
            int gk = it * BKH + c * 8;
            uint4 u = make_uint4(0, 0, 0, 0);
            if (gm < M) {
                const float* p0 = j.Ap3 + (long)gm * HH + gk;
                const float* p1 = p0 + (long)BB * NVV * HH;
                const float* p2 = p1 + (long)BB * NVV * HH;
                float4 a0 = *(const float4*)p0,      a1 = *(const float4*)(p0 + 4);
                float4 b0 = *(const float4*)p1,      b1 = *(const float4*)(p1 + 4);
                float4 c0 = *(const float4*)p2,      c1 = *(const float4*)(p2 + 4);
                float r = j.aprv[gm];
                __half2 h0 = __floats2half2_rn((a0.x + b0.x + c0.x) * r, (a0.y + b0.y + c0.y) * r);
                __half2 h1 = __floats2half2_rn((a0.z + b0.z + c0.z) * r, (a0.w + b0.w + c0.w) * r);
                __half2 h2 = __floats2half2_rn((a1.x + b1.x + c1.x) * r, (a1.y + b1.y + c1.y) * r);
                __half2 h3 = __floats2half2_rn((a1.z + b1.z + c1.z) * r, (a1.w + b1.w + c1.w) * r);
                u.x = *(unsigned*)&h0; u.y = *(unsigned*)&h1;
                u.z = *(unsigned*)&h2; u.w = *(unsigned*)&h3;
            }
            *(uint4*)&As[it & (STAGES - 1)][row * TSW + c * 4] = u;
            __syncthreads();
        }

        int nx = it + STAGES - 1;
        if (nx < ntiles) {
            unsigned aB = (unsigned)__cvta_generic_to_shared(&As[nx & (STAGES - 1)][0]);
            unsigned bB = (unsigned)__cvta_generic_to_shared(&Bs[nx & (STAGES - 1)][0]);
            issue_tile_h(j, Ab, Bb, m0, n0, nx, Kact, aB, bB, t);
        }
        cpa_commit();

        const unsigned* Asb = As[it & (STAGES - 1)];
        const unsigned* Bsb = Bs[it & (STAGES - 1)];

        #pragma unroll
        for (int kg = 0; kg < 2; kg++) {
            int kw = kg * 8;
            unsigned af[4], bf[4][2];
            int mb = wm * 16 + g;
            af[0] = Asb[mb * TSW + kw + tg];
            af[1] = Asb[(mb + 8) * TSW + kw + tg];
            af[2] = Asb[mb * TSW + kw + tg + 4];
            af[3] = Asb[(mb + 8) * TSW + kw + tg + 4];
            #pragma unroll
            for (int ni = 0; ni < 4; ni++) {
                int nb = wn * 32 + ni * 8 + g;
                bf[ni][0] = Bsb[nb * TSW + kw + tg];
                bf[ni][1] = Bsb[nb * TSW + kw + tg + 4];
            }
            #pragma unroll
            for (int ni = 0; ni < 4; ni++)
                mma16h(acc[ni], af, bf[ni]);
        }
    }

    #pragma unroll
    for (int hf = 0; hf < 2; hf++) {
        int row = m0 + wm * 16 + g + hf * 8;
        bool rok = row < M;
        float p1 = 0.f, p2 = 0.f;
        if (rok) {
            float scale = j.rowscale ? j.rowscale[bb * M + row] : 1.f;
            long tb0 = 0;
            if (j.CT) {
                int b2 = row / j.Nrow;
                int n2 = row - b2 * j.Nrow;
                tb0 = (long)b2 * HH * j.ldCT + n2;
            }
            long rowoff = coff + (long)row * N;
            #pragma unroll
            for (int ni = 0; ni < 4; ni++) {
                int col = n0 + wn * 32 + ni * 8 + tg * 2;
                if (col >= N) continue;
                float v0 = acc[ni][hf * 2 + 0] * scale;
                float v1 = acc[ni][hf * 2 + 1] * scale;
                if (j.bias) { v0 += j.bias[col]; v1 += j.bias[col + 1]; }
                long off = rowoff + col;
                if (j.resh) {
                    __half2 r = *(const __half2*)&j.resh[off];
                    float2 rf = __half22float2(r);
                    v0 += rf.x; v1 += rf.y;
                }
                if (j.relu) { v0 = v0 > 0.f ? v0 : 0.f; v1 = v1 > 0.f ? v1 : 0.f; }
                if (j.Cf) *(float2*)&j.Cf[off] = make_float2(v0, v1);
                if (j.Ch) *(__half2*)&j.Ch[off] = __floats2half2_rn(v0, v1);
                if (j.CT) {
                    long tb = tb0 + (long)col * j.ldCT;
                    j.CT[tb] = __float2half(v0);
                    j.CT[tb + j.ldCT] = __float2half(v1);
                }
                if (j.s1) {
                    p1 += v0 * j.a1[col] + v1 * j.a1[col + 1];
                    p2 += v0 * j.a2[col] + v1 * j.a2[col + 1];
                }
            }
        }
        if (j.s1) {
            p1 += __shfl_down_sync(0xffffffffu, p1, 2);
            p1 += __shfl_down_sync(0xffffffffu, p1, 1);
            p2 += __shfl_down_sync(0xffffffffu, p2, 2);
            p2 += __shfl_down_sync(0xffffffffu, p2, 1);
            if (tg == 0 && rok) {
                atomicAdd(&j.s1[row], p1);
                atomicAdd(&j.s2[row], p2);
            }
        }
    }
}

// ---------------- merged prologue: maskbuild | aovprep | cvtflat x2 | wcvt ----------------
#define NB_MASK 2000
#define NB_AOV  (16*47*BB)
#define NB_CVV  2000
#define NB_CVO  375
#define NB_W    640
#define NB_PREP (NB_MASK + NB_AOV + NB_CVV + NB_CVO + NB_W)

struct WJobs { const float* src[10]; int K[10]; int N[10]; long off[10]; };

__global__ void __launch_bounds__(256) prep(
    const float* __restrict__ adjv, const float* __restrict__ adjo,
    unsigned* __restrict__ mv, unsigned* __restrict__ mo,
    const float* __restrict__ Aov, __half* __restrict__ aov,
    __half* __restrict__ aovt, float* __restrict__ csum,
    const float* __restrict__ vism, __half* __restrict__ vismh,
    const float* __restrict__ objm, __half* __restrict__ objmh,
    WJobs w, __half* __restrict__ arena)
{
    __shared__ float tl[32][33];
    int bidx = blockIdx.x;
    int tid = threadIdx.x;

    if (bidx < NB_MASK) {
        int warp = tid >> 5, lane = tid & 31;
        long gw = (long)bidx * 8 + warp;
        const float* adj; unsigned* m; int N, W; long row;
        if (gw < (long)BB * NVV) { adj = adjv; m = mv; N = NVV; W = WV; row = gw; }
        else                     { adj = adjo; m = mo; N = NOO; W = WO; row = gw - (long)BB * NVV; }
        const float* ar = adj + row * (long)N;
        unsigned* mr = m + row * (long)W;
        int nit = (W + 3) / 4;
        for (int it = 0; it < nit; it++) {
            int j0 = it * 128 + lane * 4;
            unsigned nib = 0;
            if (j0 + 3 < N) {
                float4 a = *(const float4*)&ar[j0];
                if (a.x > 0.f) nib |= 1u;
                if (a.y > 0.f) nib |= 2u;
                if (a.z > 0.f) nib |= 4u;
                if (a.w > 0.f) nib |= 8u;
            } else {
                #pragma unroll
                for (int e = 0; e < 4; e++)
                    if (j0 + e < N && ar[j0 + e] > 0.f) nib |= 1u << e;
            }
            unsigned v = nib << ((lane & 7) * 4);
            v |= __shfl_xor_sync(0xffffffffu, v, 1);
            v |= __shfl_xor_sync(0xffffffffu, v, 2);
            v |= __shfl_xor_sync(0xffffffffu, v, 4);
            if ((lane & 7) == 0) {
                int ww = it * 4 + (lane >> 3);
                if (ww < W) mr[ww] = v;
            }
        }
        return;
    }
    bidx -= NB_MASK;
    if (bidx < NB_AOV) {
        int b = bidx / (16 * 47);
        int r2 = bidx - b * (16 * 47);
        int yb = r2 / 16;
        int xb = r2 - yb * 16;
        int v0 = xb * 32, o0 = yb * 32;
        int tx = tid & 31, ty = tid >> 5;
        const float* Ab = Aov + (long)b * NOO * NVV;
        #pragma unroll
        for (int i = 0; i < 4; i++) {
            int o = o0 + ty + i * 8, v = v0 + tx;
            tl[ty + i * 8][tx] = (o < NOO && v < NVV) ? Ab[(long)o * NVV + v] : 0.f;
        }
        __syncthreads();
        #pragma unroll
        for (int i = 0; i < 4; i++) {
            int o = o0 + ty + i * 8, v = v0 + tx;
            if (o < NOO && v < 504)
                aov[(long)b * NOO * 504 + (long)o * 504 + v] = __float2half(tl[ty + i * 8][tx]);
        }
        #pragma unroll
        for (int i = 0; i < 4; i++) {
            int v = v0 + ty + i * 8, o = o0 + tx;
            if (v < NVV)
                aovt[(long)b * NVV * 1504 + (long)v * 1504 + o] = __float2half(tl[tx][ty + i * 8]);
        }
        if (ty == 0 && v0 + tx < NVV) {
            float s = 0.f;
            #pragma unroll
            for (int o = 0; o < 32; o++) s += tl[o][tx];
            atomicAdd(&csum[b * NVV + v0 + tx], s);
        }
        return;
    }
    bidx -= NB_AOV;
    if (bidx < NB_CVV + NB_CVO) {
        const float* src; __half* dst; long n4; long i0;
        if (bidx < NB_CVV) { src = vism; dst = vismh; n4 = (long)BB * NVV * DVV / 4; i0 = (long)bidx * 256; }
        else { src = objm; dst = objmh; n4 = (long)BB * NOO * DOO / 4; i0 = (long)(bidx - NB_CVV) * 256; }
        long i = i0 + tid;
        if (i < n4) {
            float4 v = *(const float4*)&src[i * 4];
            __half2 h0 = __floats2half2_rn(v.x, v.y);
            __half2 h1 = __floats2half2_rn(v.z, v.w);
            uint2 u;
            u.x = *(unsigned*)&h0;
            u.y = *(unsigned*)&h1;
            *(uint2*)&dst[i * 4] = u;
        }
        return;
    }
    bidx -= NB_CVV + NB_CVO;
    {
        int jid = bidx / 64;
        int xb = bidx - jid * 64;
        const float* s = w.src[jid];
        int K = w.K[jid], N = w.N[jid];
        long off = w.off[jid];
        long n = (long)K * N;
        for (long idx = (long)xb * 256 + tid; idx < n; idx += 64L * 256) {
            long k = idx / N;
            int c = (int)(idx - k * N);
            arena[off + (long)c * K + k] = __float2half(s[idx]);
        }
    }
}

// ---------------- merged rvfin + rowsum (one launch) ----------------
__global__ void finprep(const float* __restrict__ rvsum, float* __restrict__ rv,
                        const __half* __restrict__ aov, float* __restrict__ to_)
{
    int bidx = blockIdx.x;
    if (bidx < 16) {
        int i = bidx * 256 + threadIdx.x;
        if (i < BB * NVV) rv[i] = 1.f / (rvsum[i] + EPSF);
        return;
    }
    int gb = bidx - 16;
    int b = gb / 188;
    int warp = threadIdx.x >> 5, lane = threadIdx.x & 31;
    int o = (gb - b * 188) * 8 + warp;
    if (o >= NOO) return;
    const __half2* row = (const __half2*)(aov + (long)b * NOO * 504 + (long)o * 504);
    const float2* rsb = (const float2*)(rvsum + b * NVV);
    float s = 0.f;
    #pragma unroll
    for (int i = 0; i < 8; i++) {
        int idx = lane + 32 * i;
        if (idx < 250) {
            float2 f = __half22float2(row[idx]);
            float2 r = rsb[idx];
            s += f.x / (r.x + EPSF) + f.y / (r.y + EPSF);
        }
    }
    #pragma unroll
    for (int off = 16; off; off >>= 1) s += __shfl_xor_sync(0xffffffffu, s, off);
    if (lane == 0) to_[b * NOO + o] = 1.f / (s + EPSF);
}

// ---------------- fp16 fused masked-softmax attention (R15 form) ----------------
#define AROWS 64
#define AJC 128
#define HS2 68
#define ATTN_SMEM_H ((128*HS2 + AROWS*HS2 + AROWS + 256) * 4)

struct AJob {
    const __half* hT; const float* s1; const float* s2;
    __half* out; __half* outT; const float* tsc;
    const unsigned* mask; int W;
    long ldT; int N; int nx; int total;
};

__global__ void __launch_bounds__(256) attn_h(AJob j0, AJob j1)
{
    extern __shared__ unsigned smu[];
    unsigned* hsT = smu;
    unsigned* wsh = smu + 128 * HS2;
    float* zrow   = (float*)(wsh + AROWS * HS2);
    float* redm   = zrow + AROWS;

    AJob j; int bid;
    if (blockIdx.x < (unsigned)j0.total) { j = j0; bid = blockIdx.x; }
    else                                 { j = j1; bid = blockIdx.x - j0.total; }
    int b  = bid / j.nx;
    int i0 = (bid - b * j.nx) * AROWS;
    int N  = j.N;

    int t = threadIdx.x;
    int warp = t >> 5, lane = t & 31;
    int g = lane >> 2, tg = lane & 3;
    int wm = warp >> 2, wn = warp & 3;

    const __half* hTb  = j.hT + (long)b * HH * j.ldT;
    const float* s2b   = j.s2  + (long)b * N;
    unsigned hsBase = (unsigned)__cvta_generic_to_shared(hsT);

    // per-block smax of s2
    {
        float m = -1e30f;
        for (int i = t; i < N; i += 256) m = fmaxf(m, s2b[i]);
        redm[t] = m;
        __syncthreads();
        #pragma unroll
        for (int s = 128; s > 0; s >>= 1) {
            if (t < s) redm[t] = fmaxf(redm[t], redm[t + s]);
            __syncthreads();
        }
    }
    float mb = redm[0];

    float acc[2][4][4];
    #pragma unroll
    for (int mi = 0; mi < 2; mi++)
        #pragma unroll
        for (int ni = 0; ni < 4; ni++)
            #pragma unroll
            for (int e = 0; e < 4; e++) acc[mi][ni][e] = 0.f;

    if (t < AROWS) zrow[t] = 0.f;

    int pr = t >> 2;
    int pj = (t & 3) * 32;
    int prow = i0 + pr;
    float s1r = 0.f, mrow = 0.f;
    if (prow < N) {
        s1r = j.s1[(long)b * N + prow];
        float x = s1r + mb;
        mrow = x > 0.f ? x : 0.2f * x;
    }

    int sf = t >> 1;
    int ss = (t & 1) * 64;

    for (int c0 = 0; c0 < N; c0 += AJC) {
        __syncthreads();

        {
            const __half* src = hTb + (long)sf * j.ldT + c0 + ss;
            unsigned dst = hsBase + (unsigned)(sf * HS2) * 4u + (unsigned)ss * 2u;
            #pragma unroll
            for (int s = 0; s < 8; s++)
                cpa16(dst + s * 16u, src + s * 8, 16);
            cpa_commit();
        }

        float zl = 0.f;
        if (prow < N) {
            long mbase = ((long)b * N + prow) * j.W + (c0 >> 5) + (t & 3);
            int wbase = pr * HS2 + (pj >> 1);
            unsigned mw = j.mask[mbase];
            if (mw) {
                #pragma unroll
                for (int q4 = 0; q4 < 32; q4 += 4) {
                    int jj = pj + q4;
                    int gj = c0 + jj;
                    float sv[4];
                    if (gj + 3 < N) {
                        float4 s4 = *(const float4*)&s2b[gj];
                        sv[0]=s4.x; sv[1]=s4.y; sv[2]=s4.z; sv[3]=s4.w;
                    } else {
                        #pragma unroll
                        for (int e = 0; e < 4; e++)
                            sv[e] = (gj + e) < N ? s2b[gj + e] : 0.f;
                    }
                    float w[4];
                    #pragma unroll
                    for (int e = 0; e < 4; e++) {
                        w[e] = 0.f;
                        if ((mw >> (q4 + e)) & 1u) {
                            float x = s1r + sv[e];
                            float ev = x > 0.f ? x : 0.2f * x;
                            w[e] = __expf(ev - mrow);
                        }
                    }
                    __half2 u0 = __floats2half2_rn(w[0], w[1]);
                    __half2 u1 = __floats2half2_rn(w[2], w[3]);
                    *(__half2*)&wsh[wbase + (q4 >> 1)]     = u0;
                    *(__half2*)&wsh[wbase + (q4 >> 1) + 1] = u1;
                    float2 f0 = __half22float2(u0), f1 = __half22float2(u1);
                    zl += f0.x + f0.y + f1.x + f1.y;
                }
            } else {
                #pragma unroll
                for (int q = 0; q < 16; q++) wsh[wbase + q] = 0u;
            }
        } else {
            int wbase = pr * HS2 + (pj >> 1);
            #pragma unroll
            for (int q = 0; q < 16; q++) wsh[wbase + q] = 0u;
        }
        zl += __shfl_down_sync(0xffffffffu, zl, 2);
        zl += __shfl_down_sync(0xffffffffu, zl, 1);
        if ((t & 3) == 0 && prow < N) zrow[pr] += zl;

        asm volatile("cp.async.wait_group 0;");
        __syncthreads();

        #pragma unroll
        for (int kg = 0; kg < 8; kg++) {
            int kw = kg * 8;
            unsigned af[2][4], bf[4][2];
            #pragma unroll
            for (int mi = 0; mi < 2; mi++) {
                int mr = wm * 32 + mi * 16 + g;
                af[mi][0] = wsh[mr * HS2 + kw + tg];
                af[mi][1] = wsh[(mr + 8) * HS2 + kw + tg];
                af[mi][2] = wsh[mr * HS2 + kw + tg + 4];
                af[mi][3] = wsh[(mr + 8) * HS2 + kw + tg + 4];
            }
            #pragma unroll
            for (int ni = 0; ni < 4; ni++) {
                int nr = wn * 32 + ni * 8 + g;
                bf[ni][0] = hsT[nr * HS2 + kw + tg];
                bf[ni][1] = hsT[nr * HS2 + kw + tg + 4];
            }
            #pragma unroll
            for (int mi = 0; mi < 2; mi++)
                #pragma unroll
                for (int ni = 0; ni < 4; ni++)
                    mma16h(acc[mi][ni], af[mi], bf[ni]);
        }
    }
    __syncthreads();

    long tbb = (long)b * HH * j.ldT;
    #pragma unroll
    for (int mi = 0; mi < 2; mi++) {
        #pragma unroll
        for (int hf = 0; hf < 2; hf++) {
            int r0 = wm * 32 + mi * 16 + g + hf * 8;
            int row = i0 + r0;
            if (row >= N) continue;
            float inv = 1.f / zrow[r0];
            float rs = j.tsc ? j.tsc[(long)b * N + row] : 1.f;
            long tb0 = tbb + row;
            #pragma unroll
            for (int ni = 0; ni < 4; ni++) {
                int col = wn * 32 + ni * 8 + tg * 2;
                float v0 = acc[mi][ni][hf * 2 + 0] * inv;
                float v1 = acc[mi][ni][hf * 2 + 1] * inv;
                v0 = v0 > 0.f ? v0 : 0.f;
                v1 = v1 > 0.f ? v1 : 0.f;
                long off = (long)b * N * HH + (long)row * HH + col;
                *(__half2*)&j.out[off] = __floats2half2_rn(v0, v1);
                j.outT[tb0 + (long)col * j.ldT]       = __float2half(v0 * rs);
                j.outT[tb0 + (long)(col + 1) * j.ldT] = __float2half(v1 * rs);
            }
        }
    }
}

// ---------------- host orchestration ----------------
static GJ mkjob(const __half* A, const __half* Bt, float* Cf, __half* Ch,
                const float* bias, const __half* resh, const float* rowscale,
                int M, int N, int K, int KpA, int KpB,
                long sA, long sB, long sC, int relu, int nbat)
{
    GJ j;
    j.A = A; j.Bt = Bt; j.Cf = Cf; j.Ch = Ch;
    j.CT = nullptr; j.ldCT = 0; j.Nrow = 1;
    j.s1 = nullptr; j.s2 = nullptr; j.a1 = nullptr; j.a2 = nullptr;
    j.Ap3 = nullptr; j.aprv = nullptr;
    j.bias = bias; j.resh = resh; j.rowscale = rowscale;
    j.M = M; j.N = N; j.Ktot = K; j.Ksplit = K;
    j.KpA = KpA; j.KpB = KpB;
    j.sA = sA; j.sB = sB; j.sC = sC;
    j.spA = 0; j.spB = 0; j.spC = 0;
    j.nbat = nbat; j.nsplit = 1; j.relu = relu;
    j.gx = (N + TBN - 1) / TBN;
    j.gy = (M + TBM - 1) / TBM;
    j.total = j.gx * j.gy * nbat;
    return j;
}

static void launch_gemm2(const GJ& a, const GJ& b)
{
    gemm_h<<<a.total + b.total, 256>>>(a, b);
}

extern "C" void kernel_launch(void* const* d_in, const int* in_sizes, int n_in,
                              void* d_out, int out_size)
{
    const float* vis_memory = (const float*)d_in[0];
    const float* obj_memory = (const float*)d_in[1];
    const float* vis_adj    = (const float*)d_in[2];
    const float* obj_adj    = (const float*)d_in[3];
    const float* A_OV       = (const float*)d_in[4];
    const float* Wv1  = (const float*)d_in[5];
    const float* av1a = (const float*)d_in[6];
    const float* av1b = (const float*)d_in[7];
    const float* Wv2  = (const float*)d_in[8];
    const float* av2a = (const float*)d_in[9];
    const float* av2b = (const float*)d_in[10];
    const float* Wo1  = (const float*)d_in[11];
    const float* ao1a = (const float*)d_in[12];
    const float* ao1b = (const float*)d_in[13];
    const float* Wo2  = (const float*)d_in[14];
    const float* ao2a = (const float*)d_in[15];
    const float* ao2b = (const float*)d_in[16];
    const float* g2o_W1 = (const float*)d_in[17];
    const float* g2o_b1 = (const float*)d_in[18];
    const float* g2o_W2 = (const float*)d_in[19];
    const float* g2o_b2 = (const float*)d_in[20];
    const float* o2g_W1 = (const float*)d_in[21];
    const float* o2g_b1 = (const float*)d_in[22];
    const float* o2g_W2 = (const float*)d_in[23];
    const float* o2g_b2 = (const float*)d_in[24];
    const float* img_W = (const float*)d_in[25];
    const float* img_b = (const float*)d_in[26];
    const float* obj_W = (const float*)d_in[27];
    const float* obj_b = (const float*)d_in[28];

    float *p_cvp, *p_zbuf, *p_rv, *p_to;
    unsigned *p_mv, *p_mo;
    __half *ph_vism, *ph_objm, *ph_aov, *ph_aovt, *ph_oT, *ph_vT, *ph_hvT, *ph_hoT;
    __half *ph_v, *ph_o, *ph_co, *ph_m1v, *ph_m1o, *ph_vis, *ph_obj, *ph_wt;

    cudaGetSymbolAddress((void**)&p_cvp, g_cvp);
    cudaGetSymbolAddress((void**)&p_zbuf, g_zbuf);
    cudaGetSymbolAddress((void**)&p_rv,  g_rv);
    cudaGetSymbolAddress((void**)&p_to,  g_to);
    cudaGetSymbolAddress((void**)&p_mv,  g_mv);
    cudaGetSymbolAddress((void**)&p_mo,  g_mo);
    cudaGetSymbolAddress((void**)&ph_vism, h_vism);
    cudaGetSymbolAddress((void**)&ph_objm, h_objm);
    cudaGetSymbolAddress((void**)&ph_aov,  h_aov);
    cudaGetSymbolAddress((void**)&ph_aovt, h_aovt);
    cudaGetSymbolAddress((void**)&ph_oT,   h_oT);
    cudaGetSymbolAddress((void**)&ph_vT,   h_vT);
    cudaGetSymbolAddress((void**)&ph_hvT,  h_hvT);
    cudaGetSymbolAddress((void**)&ph_hoT,  h_hoT);
    cudaGetSymbolAddress((void**)&ph_v,    h_v);
    cudaGetSymbolAddress((void**)&ph_o,    h_o);
    cudaGetSymbolAddress((void**)&ph_co,   h_co);
    cudaGetSymbolAddress((void**)&ph_m1v,  h_m1v);
    cudaGetSymbolAddress((void**)&ph_m1o,  h_m1o);
    cudaGetSymbolAddress((void**)&ph_vis,  h_vis);
    cudaGetSymbolAddress((void**)&ph_obj,  h_obj);
    cudaGetSymbolAddress((void**)&ph_wt,   g_wt);

    float* p_rvsum = p_zbuf;
    float* ps1v = p_zbuf + 4000;
    float* ps2v = p_zbuf + 12000;
    float* ps1o = p_zbuf + 20000;
    float* ps2o = p_zbuf + 44000;

    cudaFuncSetAttribute(attn_h, cudaFuncAttributeMaxDynamicSharedMemorySize, ATTN_SMEM_H);

    // ---- prologue: memset + prep + finprep (3 launches) ----
    cudaMemsetAsync(p_zbuf, 0, 68000 * sizeof(float));
    {
        WJobs w;
        const float* srcs[10] = { Wv1, Wv2, Wo1, Wo2, o2g_W1, o2g_W2, g2o_W1, g2o_W2, img_W, obj_W };
        int Ks[10] = { 512, 128, 32, 128, 128, 128, 128, 128, 128, 128 };
        int Ns[10] = { 128, 128, 128, 128, 128, 128, 128, 128, 512, 32 };
        long offs[10] = { WT_WV1, WT_WV2, WT_WO1, WT_WO2, WT_O2G1, WT_O2G2,
                          WT_G2O1, WT_G2O2, WT_IMG, WT_OBJ };
        for (int i = 0; i < 10; i++) { w.src[i] = srcs[i]; w.K[i] = Ks[i]; w.N[i] = Ns[i]; w.off[i] = offs[i]; }
        prep<<<NB_PREP, 256>>>(vis_adj, obj_adj, p_mv, p_mo,
                               A_OV, ph_aov, ph_aovt, p_rvsum,
                               vis_memory, ph_vism, obj_memory, ph_objm,
                               w, ph_wt);
    }
    finprep<<<16 + 188 * BB, 256>>>(p_rvsum, p_rv, ph_aov, p_to);

    for (int round = 0; round < 2; round++) {
        const __half* xv = (round == 0) ? ph_vism : ph_vis;
        const __half* xo = (round == 0) ? ph_objm : ph_obj;
        int Kv = (round == 0) ? DVV : HH;
        int Ko = (round == 0) ? DOO : HH;
        const __half* Wvt = ph_wt + ((round == 0) ? WT_WV1 : WT_WV2);
        const __half* Wot = ph_wt + ((round == 0) ? WT_WO1 : WT_WO2);
        const float* ava = (round == 0) ? av1a : av2a;
        const float* avb = (round == 0) ? av1b : av2b;
        const float* aoa = (round == 0) ? ao1a : ao2a;
        const float* aob = (round == 0) ? ao1b : ao2b;
        float* s1v = ps1v + round * BB * NVV;
        float* s2v = ps2v + round * BB * NVV;
        float* s1o = ps1o + round * BB * NOO;
        float* s2o = ps2o + round * BB * NOO;

        // h = x @ W  (transposed fp16 out + fused scores)
        {
            GJ jv = mkjob(xv, Wvt, nullptr, nullptr, nullptr, nullptr, nullptr,
                          BB * NVV, HH, Kv, Kv, Kv, 0, 0, 0, 0, 1);
            jv.CT = ph_hvT; jv.ldCT = 504; jv.Nrow = NVV;
            jv.s1 = s1v; jv.s2 = s2v; jv.a1 = ava; jv.a2 = avb;
            GJ jo = mkjob(xo, Wot, nullptr, nullptr, nullptr, nullptr, nullptr,
                          BB * NOO, HH, Ko, Ko, Ko, 0, 0, 0, 0, 1);
            jo.CT = ph_hoT; jo.ldCT = 1504; jo.Nrow = NOO;
            jo.s1 = s1o; jo.s2 = s2o; jo.a1 = aoa; jo.a2 = aob;
            launch_gemm2(jv, jo);
        }

        // attention (fp16 mma, mask-based, in-block smax); obj job first
        {
            int nxv = (NVV + AROWS - 1) / AROWS;
            int nxo = (NOO + AROWS - 1) / AROWS;
            AJob ao_ = { ph_hoT, s1o, s2o, ph_o, ph_oT, nullptr,
                         p_mo, WO, 1504, NOO, nxo, nxo * BB };
            AJob av_ = { ph_hvT, s1v, s2v, ph_v, ph_vT, p_rv,
                         p_mv, WV, 504, NVV, nxv, nxv * BB };
            attn_h<<<ao_.total + av_.total, 256, ATTN_SMEM_H>>>(ao_, av_);
        }

        // cv partials (split-K x3 @512) || co = to ⊙ (A_OV @ (rv⊙v))
        {
            GJ jcv = mkjob(ph_aovt, ph_oT, p_cvp, nullptr, nullptr, nullptr, nullptr,
                           NVV, HH, NOO, 1504, 1504,
                           (long)NVV * 1504, (long)HH * 1504, (long)NVV * HH, 0, BB);
            jcv.Ksplit = 512; jcv.nsplit = 3;
            jcv.spA = 512; jcv.spB = 512; jcv.spC = (long)BB * NVV * HH;
            jcv.total = jcv.gx * jcv.gy * BB * 3;
            GJ jco = mkjob(ph_aov, ph_vT, nullptr, ph_co, nullptr, nullptr, p_to,
                           NOO, HH, NVV, 504, 504,
                           (long)NOO * 504, (long)HH * 504, (long)NOO * HH, 0, BB);
            launch_gemm2(jcv, jco);
        }

        // mlp layer 1 (relu); vis job reads cv-partials fused (Ap3)
        {
            GJ jv = mkjob(nullptr, ph_wt + WT_O2G1, nullptr, ph_m1v, o2g_b1, nullptr, nullptr,
                          BB * NVV, HH, HH, HH, HH, 0, 0, 0, 1, 1);
            jv.Ap3 = p_cvp; jv.aprv = p_rv;
            GJ jo = mkjob(ph_co, ph_wt + WT_G2O1, nullptr, ph_m1o, g2o_b1, nullptr, nullptr,
                          BB * NOO, HH, HH, HH, HH, 0, 0, 0, 1, 1);
            launch_gemm2(jv, jo);
        }

        // mlp layer 2 + fp16 residual
        launch_gemm2(
            mkjob(ph_m1v, ph_wt + WT_O2G2, nullptr, ph_vis, o2g_b2, ph_v, nullptr,
                  BB * NVV, HH, HH, HH, HH, 0, 0, 0, 0, 1),
            mkjob(ph_m1o, ph_wt + WT_G2O2, nullptr, ph_obj, g2o_b2, ph_o, nullptr,
                  BB * NOO, HH, HH, HH, HH, 0, 0, 0, 0, 1));
    }

    // output projections
    float* out_vis = (float*)d_out;
    float* out_obj = out_vis + (long)BB * NVV * DVV;
    launch_gemm2(
        mkjob(ph_vis, ph_wt + WT_IMG, out_vis, nullptr, img_b, nullptr, nullptr,
              BB * NVV, DVV, HH, HH, HH, 0, 0, 0, 0, 1),
        mkjob(ph_obj, ph_wt + WT_OBJ, out_obj, nullptr, obj_b, nullptr, nullptr,
              BB * NOO, DOO, HH, HH, HH, 0, 0, 0, 0, 1));
}